// round 13
// baseline (speedup 1.0000x reference)
#include <cuda_runtime.h>
#include <cuda_fp16.h>
#include <cstdint>

typedef unsigned long long ull;

// ---------------- device scratch (no runtime allocation allowed) ----------------
__device__ float  gS[32 * 64 * 9];     // strided sums for cond conv
__device__ float  gDw[32 * 576];       // per-sample depthwise weights (fp32)
__device__ __half gPwH[32 * 4096];     // per-sample pointwise weights [b][o][c], fp16
__device__ float  gDb[32 * 64];        // per-sample dynamic bias
__device__ double gSum[64], gSumSq[64];// BN statistics accumulators
__device__ __half gOut16[32 * 64 * 16384];   // pre-BN intermediate (fp16, 67 MB)

// =================================================================================
// Kernel 1: per-(b,c) 9 strided sums S[kh][kw] = sum_{oh,ow} x[2oh+kh, 2ow+kw]
// =================================================================================
__global__ void __launch_bounds__(256) k_cond_sums(const float* __restrict__ x) {
    int bc = blockIdx.x;                 // b*64 + c
    int t  = threadIdx.x;
    const float* base = x + (size_t)bc * 16384;

    int i  = t >> 1;                     // row 0..127
    int j0 = (t & 1) * 64;               // half-row
    const float4* row4 = (const float4*)(base + i * 128 + j0);

    float ca0 = 0.f, ca1 = 0.f, ca2 = 0.f;
#pragma unroll
    for (int k = 0; k < 16; k++) {
        float4 v = row4[k];
        int j = j0 + 4 * k;
        ca0 += v.x + ((j <= 122) ? v.z : 0.f);
        ca1 += v.y + ((j <= 122) ? v.w : 0.f);
        ca2 += ((j >= 2) ? v.x : 0.f) + v.z;
    }
    bool ev = ((i & 1) == 0);
    float f0 = (ev  && i <= 124) ? 1.f : 0.f;
    float f1 = (!ev && i <= 125) ? 1.f : 0.f;
    float f2 = (ev  && i >= 2)   ? 1.f : 0.f;

    float bins[9] = { f0*ca0, f0*ca1, f0*ca2,
                      f1*ca0, f1*ca1, f1*ca2,
                      f2*ca0, f2*ca1, f2*ca2 };
#pragma unroll
    for (int off = 16; off; off >>= 1)
#pragma unroll
        for (int k = 0; k < 9; k++)
            bins[k] += __shfl_down_sync(0xffffffffu, bins[k], off);

    __shared__ float red[8][9];
    int lane = t & 31, w = t >> 5;
    if (lane == 0)
#pragma unroll
        for (int k = 0; k < 9; k++) red[w][k] = bins[k];
    __syncthreads();
    if (t < 9) {
        float s = 0.f;
#pragma unroll
        for (int ww = 0; ww < 8; ww++) s += red[ww][t];
        gS[bc * 9 + t] = s;
    }
}

// =================================================================================
// Kernel 2: condition vector + dynamic weights (tiny GEMMs) + stat zeroing
// =================================================================================
__global__ void __launch_bounds__(256) k_gen(
    const float* __restrict__ cg_w1, const float* __restrict__ cg_b1,
    const float* __restrict__ cg_w2, const float* __restrict__ cg_b2,
    const float* __restrict__ wg_w,  const float* __restrict__ wg_b,
    const float* __restrict__ pg_w,  const float* __restrict__ pg_b,
    const float* __restrict__ bg_w,  const float* __restrict__ bg_b)
{
    __shared__ float Ss[576];
    __shared__ float parts[256];
    __shared__ float c0[16];
    __shared__ float cond[16];

    int b = blockIdx.x;
    int t = threadIdx.x;

    // zero BN stat accumulators (runs before k_main in-stream; deterministic)
    if (b == 0 && t < 64) { gSum[t] = 0.0; gSumSq[t] = 0.0; }

    for (int idx = t; idx < 576; idx += 256) Ss[idx] = gS[b * 576 + idx];
    __syncthreads();

    {
        int co = t >> 4, part = t & 15;
        const float* wrow = cg_w1 + co * 576 + part * 36;
        const float* srow = Ss + part * 36;
        float s = 0.f;
#pragma unroll
        for (int k = 0; k < 36; k++) s += wrow[k] * srow[k];
        parts[t] = s;
    }
    __syncthreads();
    if (t < 16) {
        float s = 0.f;
#pragma unroll
        for (int p = 0; p < 16; p++) s += parts[t * 16 + p];
        s = s * (1.0f / 3969.0f) + cg_b1[t];
        c0[t] = fmaxf(s, 0.f);
    }
    __syncthreads();
    if (t < 16) {
        float s = cg_b2[t];
#pragma unroll
        for (int i = 0; i < 16; i++) s += c0[i] * cg_w2[t * 16 + i];
        cond[t] = fmaxf(s, 0.f);
    }
    __syncthreads();

    for (int r = t; r < 576; r += 256) {
        float s = wg_b[r];
        const float* wr = wg_w + r * 16;
#pragma unroll
        for (int q = 0; q < 16; q++) s += cond[q] * wr[q];
        gDw[b * 576 + r] = fmaxf(s, 0.f);
    }
    // pointwise weights [b][o][c], fp16 for the HMMA path
    for (int r = t; r < 4096; r += 256) {
        float s = pg_b[r];
        const float* wr = pg_w + r * 16;
#pragma unroll
        for (int q = 0; q < 16; q++) s += cond[q] * wr[q];
        gPwH[b * 4096 + r] = __float2half(fmaxf(s, 0.f));
    }
    if (t < 64) {
        float s = bg_b[t];
        const float* wr = bg_w + t * 16;
#pragma unroll
        for (int q = 0; q < 16; q++) s += cond[q] * wr[q];
        gDb[b * 64 + t] = s;
    }
}

// =================================================================================
// Kernel 3: fused depthwise3x3 + fp16 MMA (m16n8k16) pointwise, HS=2 rows per CTA.
//   512 threads; 3 CTAs/SM; grid (64, 32). Writes fp16 pre-BN tensor.
// smem (floats):
//   ysH [2 row][32 c2][136 half2]  offset 0     (8704 fl)   pair-interleaved fp16 y
//   pwH [64 o][72 half]            offset 8704  (2304 fl)
//   dws [64 c][12]                 offset 11008 (768 fl)
//   dbs [64]                       offset 11776
//   sst [128]                      offset 11840  -> 11968 fl = 47872 B
// =================================================================================
__global__ void __launch_bounds__(512, 3) k_main(const float* __restrict__ x)
{
    extern __shared__ float sm[];
    char*  ysB = (char*)sm;                       // byte base of ysH
    const uint32_t* pw32 = (const uint32_t*)(sm + 8704);  // pwH as u32 (2 halves)
    float* dws = sm + 11008;
    float* dbs = sm + 11776;
    float* sst = sm + 11840;

    int tid  = threadIdx.x;
    int lane = tid & 31, wid = tid >> 5;
    int h0 = blockIdx.x * 2, b = blockIdx.y;

    // ---- stage per-sample dynamic weights into smem ----
    {
        // pw fp16: 4096 halves = 512 uint4; pad rows to 72 halves (144 B)
        const uint4* src = (const uint4*)(gPwH + b * 4096);
        uint4 v = src[tid];
        int o = tid >> 3, j = tid & 7;
        *(uint4*)((char*)(sm + 8704) + o * 144 + j * 16) = v;

        for (int idx = tid; idx < 576; idx += 512) {
            int c = idx / 9, jj = idx - 9 * c;
            dws[c * 12 + jj] = gDw[b * 576 + idx];
        }
        if (tid < 64) dbs[tid] = gDb[b * 64 + tid];
        else if (tid >= 64 && tid < 192) sst[tid - 64] = 0.f;
    }
    __syncthreads();

    // ---- depthwise 3x3 (pad=1); warp w: channels [4w,4w+4) = 2 pairs; 2 rows ----
    const float4* xb = (const float4*)(x + (size_t)b * 64 * 16384);
    const float4 z4 = make_float4(0.f, 0.f, 0.f, 0.f);
    bool hasT = (h0 >= 1), hasB = (h0 <= 125);

#pragma unroll
    for (int pr = 0; pr < 2; pr++) {
        float rE[2][4], rO[2][4];
#pragma unroll
        for (int half = 0; half < 2; half++) {
            int c = wid * 4 + pr * 2 + half;
            const float4* plane = xb + (size_t)c * 4096;
            float4 m[4];
            m[0] = hasT ? plane[(h0 - 1) * 32 + lane] : z4;
            m[1] =        plane[h0       * 32 + lane];
            m[2] =        plane[(h0 + 1) * 32 + lane];
            m[3] = hasB ? plane[(h0 + 2) * 32 + lane] : z4;

            float lf[4], rg[4];
#pragma unroll
            for (int i = 0; i < 4; i++) {
                lf[i] = __shfl_up_sync(0xffffffffu, m[i].w, 1);
                rg[i] = __shfl_down_sync(0xffffffffu, m[i].x, 1);
                if (lane == 0)  lf[i] = 0.f;
                if (lane == 31) rg[i] = 0.f;
            }

            const float* wp = dws + c * 12;
            float4 wA = *(const float4*)(wp);       // w00 w01 w02 w10
            float4 wB = *(const float4*)(wp + 4);   // w11 w12 w20 w21
            float  w8 = wp[8];                      // w22

#pragma unroll
            for (int row = 0; row < 2; row++) {
                float a0 = 0.f, a1 = 0.f, a2 = 0.f, a3 = 0.f;
#pragma unroll
                for (int r = 0; r < 3; r++) {
                    int i = row + r;
                    float w0 = (r == 0) ? wA.x : (r == 1) ? wA.w : wB.z;
                    float w1 = (r == 0) ? wA.y : (r == 1) ? wB.x : wB.w;
                    float w2 = (r == 0) ? wA.z : (r == 1) ? wB.y : w8;
                    a0 += w0 * lf[i]  + w1 * m[i].x + w2 * m[i].y;
                    a1 += w0 * m[i].x + w1 * m[i].y + w2 * m[i].z;
                    a2 += w0 * m[i].y + w1 * m[i].z + w2 * m[i].w;
                    a3 += w0 * m[i].z + w1 * m[i].w + w2 * rg[i];
                }
                float* dst = half ? rO[row] : rE[row];
                dst[0] = a0; dst[1] = a1; dst[2] = a2; dst[3] = a3;
            }
        }
        // pack channel pair -> half2 (low = even channel = lower k) and store
        int c2 = wid * 2 + pr;
#pragma unroll
        for (int row = 0; row < 2; row++) {
            __half2 h0p = __floats2half2_rn(rE[row][0], rO[row][0]);
            __half2 h1p = __floats2half2_rn(rE[row][1], rO[row][1]);
            __half2 h2p = __floats2half2_rn(rE[row][2], rO[row][2]);
            __half2 h3p = __floats2half2_rn(rE[row][3], rO[row][3]);
            uint4 v;
            v.x = *(uint32_t*)&h0p; v.y = *(uint32_t*)&h1p;
            v.z = *(uint32_t*)&h2p; v.w = *(uint32_t*)&h3p;
            *(uint4*)(ysB + row * 17408 + c2 * 544 + lane * 16) = v;
        }
    }
    __syncthreads();

    // ---- fp16 MMA pointwise: warp -> (row, mt, nb); M32 x N32 tile ----
    int row = wid >> 3, mt = (wid >> 2) & 1, nb = wid & 3;
    int ob = mt * 32, wbase = nb * 32;
    int g = lane >> 2, t4 = lane & 3;
    const char* ysr = ysB + row * 17408;

    float acc[2][4][4];
#pragma unroll
    for (int ms = 0; ms < 2; ms++)
#pragma unroll
        for (int n = 0; n < 4; n++)
#pragma unroll
            for (int j = 0; j < 4; j++) acc[ms][n][j] = 0.f;

#pragma unroll
    for (int k = 0; k < 4; k++) {              // K = 16 per step
        uint32_t a[2][4];
#pragma unroll
        for (int ms = 0; ms < 2; ms++) {
            int r0 = (ob + 16 * ms + g) * 36 + 8 * k + t4;   // u32 units, pitch 36
            a[ms][0] = pw32[r0];                 // (row g,   cols 2t4,2t4+1)
            a[ms][2] = pw32[r0 + 4];             // (row g,   cols +8)
            a[ms][1] = pw32[r0 + 8 * 36];        // (row g+8, cols 2t4,2t4+1)
            a[ms][3] = pw32[r0 + 8 * 36 + 4];    // (row g+8, cols +8)
        }
        const char* bR = ysr + (8 * k + t4) * 544;
#pragma unroll
        for (int n = 0; n < 4; n++) {
            int col = (wbase + 8 * n + g) * 4;
            uint32_t b0 = *(const uint32_t*)(bR + col);            // rows 2t4,2t4+1
            uint32_t b1 = *(const uint32_t*)(bR + 4 * 544 + col);  // rows +8
#pragma unroll
            for (int ms = 0; ms < 2; ms++) {
                asm("mma.sync.aligned.m16n8k16.row.col.f32.f16.f16.f32 "
                    "{%0,%1,%2,%3}, {%4,%5,%6,%7}, {%8,%9}, {%0,%1,%2,%3};"
                    : "+f"(acc[ms][n][0]), "+f"(acc[ms][n][1]),
                      "+f"(acc[ms][n][2]), "+f"(acc[ms][n][3])
                    : "r"(a[ms][0]), "r"(a[ms][1]), "r"(a[ms][2]), "r"(a[ms][3]),
                      "r"(b0), "r"(b1));
            }
        }
    }

    // ---- epilogue: +dbias, store fp16, BN partial stats (fp32) ----
    __half* outb = gOut16 + (size_t)(b * 64) * 16384 + (size_t)(h0 + row) * 128;
    float sAcc[2][2], s2Acc[2][2];
#pragma unroll
    for (int ms = 0; ms < 2; ms++) {
        sAcc[ms][0] = 0.f; sAcc[ms][1] = 0.f;
        s2Acc[ms][0] = 0.f; s2Acc[ms][1] = 0.f;
    }

#pragma unroll
    for (int ms = 0; ms < 2; ms++) {
        int rLo = ob + 16 * ms + g;
        float dbLo = dbs[rLo], dbHi = dbs[rLo + 8];
        size_t oLo = (size_t)rLo * 16384;
        size_t oHi = (size_t)(rLo + 8) * 16384;
#pragma unroll
        for (int n = 0; n < 4; n++) {
            int w = wbase + 8 * n + 2 * t4;
            float v0 = acc[ms][n][0] + dbLo;
            float v1 = acc[ms][n][1] + dbLo;
            float v2 = acc[ms][n][2] + dbHi;
            float v3 = acc[ms][n][3] + dbHi;
            *(__half2*)(outb + oLo + w) = __floats2half2_rn(v0, v1);
            *(__half2*)(outb + oHi + w) = __floats2half2_rn(v2, v3);
            sAcc[ms][0]  += v0 + v1;            s2Acc[ms][0] += v0 * v0 + v1 * v1;
            sAcc[ms][1]  += v2 + v3;            s2Acc[ms][1] += v2 * v2 + v3 * v3;
        }
    }
#pragma unroll
    for (int off = 1; off <= 2; off <<= 1)
#pragma unroll
        for (int ms = 0; ms < 2; ms++)
#pragma unroll
            for (int hl = 0; hl < 2; hl++) {
                sAcc[ms][hl]  += __shfl_xor_sync(0xffffffffu, sAcc[ms][hl],  off);
                s2Acc[ms][hl] += __shfl_xor_sync(0xffffffffu, s2Acc[ms][hl], off);
            }
    if (t4 == 0) {
#pragma unroll
        for (int ms = 0; ms < 2; ms++)
#pragma unroll
            for (int hl = 0; hl < 2; hl++) {
                int o = ob + 16 * ms + 8 * hl + g;
                atomicAdd(&sst[o],      sAcc[ms][hl]);
                atomicAdd(&sst[64 + o], s2Acc[ms][hl]);
            }
    }

    __syncthreads();
    if (tid < 64)       atomicAdd(&gSum[tid],        (double)sst[tid]);
    else if (tid < 128) atomicAdd(&gSumSq[tid - 64], (double)sst[tid]);
}

// =================================================================================
// Kernel 4: BN finalize (per-block, from global stats) + apply
//   reads fp16 scratch (streaming), writes f32 out (streaming); MLP=8
// =================================================================================
__global__ void __launch_bounds__(256) k_bn(float* __restrict__ out,
                                            const float* __restrict__ gamma,
                                            const float* __restrict__ beta)
{
    __shared__ float scS[64], shS[64];
    int t = threadIdx.x;
    if (t < 64) {
        const double n = 524288.0;   // 32 * 128 * 128
        double mean = gSum[t] / n;
        double var  = gSumSq[t] / n - mean * mean;
        double inv  = 1.0 / sqrt(var + 1e-5);
        double gg   = (double)gamma[t];
        scS[t] = (float)(gg * inv);
        shS[t] = (float)((double)beta[t] - mean * gg * inv);
    }
    __syncthreads();

    int base = blockIdx.x * 2048 + threadIdx.x;
    const uint2* src = (const uint2*)gOut16;     // 4 halves per uint2 == 1 float4 slot
    uint2 raw[8];
#pragma unroll
    for (int j = 0; j < 8; j++) raw[j] = __ldcs(src + base + 256 * j);
#pragma unroll
    for (int j = 0; j < 8; j++) {
        int idx = base + 256 * j;
        __half2 hA = *(__half2*)&raw[j].x;
        __half2 hB = *(__half2*)&raw[j].y;
        float2 fA = __half22float2(hA);
        float2 fB = __half22float2(hB);
        int o = (idx >> 12) & 63;                // 4096 float4 per (b,o) plane
        float sc = scS[o], sh = shS[o];
        float4 v;
        v.x = fmaf(fA.x, sc, sh);
        v.y = fmaf(fA.y, sc, sh);
        v.z = fmaf(fB.x, sc, sh);
        v.w = fmaf(fB.y, sc, sh);
        __stcs((float4*)out + idx, v);
    }
}

// =================================================================================
extern "C" void kernel_launch(void* const* d_in, const int* in_sizes, int n_in,
                              void* d_out, int out_size)
{
    const float* x      = (const float*)d_in[0];
    const float* cg_w1  = (const float*)d_in[1];
    const float* cg_b1  = (const float*)d_in[2];
    const float* cg_w2  = (const float*)d_in[3];
    const float* cg_b2  = (const float*)d_in[4];
    const float* wg_w   = (const float*)d_in[5];
    const float* wg_b   = (const float*)d_in[6];
    const float* pg_w   = (const float*)d_in[7];
    const float* pg_b   = (const float*)d_in[8];
    const float* bg_w   = (const float*)d_in[9];
    const float* bg_b   = (const float*)d_in[10];
    const float* bn_g   = (const float*)d_in[11];
    const float* bn_b   = (const float*)d_in[12];
    float* out = (float*)d_out;

    cudaFuncSetAttribute(k_main, cudaFuncAttributeMaxDynamicSharedMemorySize, 47872);

    k_cond_sums<<<2048, 256>>>(x);
    k_gen<<<32, 256>>>(cg_w1, cg_b1, cg_w2, cg_b2, wg_w, wg_b, pg_w, pg_b, bg_w, bg_b);
    dim3 g3(64, 32);
    k_main<<<g3, 512, 47872>>>(x);
    k_bn<<<4096, 256>>>(out, bn_g, bn_b);
}

// round 14
// speedup vs baseline: 1.1541x; 1.1541x over previous
#include <cuda_runtime.h>
#include <cuda_fp16.h>
#include <cstdint>

typedef unsigned long long ull;

// ---------------- device scratch (no runtime allocation allowed) ----------------
__device__ float  gS[32 * 64 * 9];     // strided sums for cond conv
__device__ float  gDw[32 * 576];       // per-sample depthwise weights (fp32)
__device__ __half gPwH[32 * 4096];     // per-sample pointwise weights [b][o][c], fp16
__device__ float  gDb[32 * 64];        // per-sample dynamic bias
__device__ double gSum[64], gSumSq[64];// BN statistics accumulators
__device__ __half gOut16[32 * 64 * 16384];   // pre-BN intermediate (fp16, 67 MB)

// =================================================================================
// Kernel 1: per-(b,c) 9 strided sums S[kh][kw] = sum_{oh,ow} x[2oh+kh, 2ow+kw]
// =================================================================================
__global__ void __launch_bounds__(256) k_cond_sums(const float* __restrict__ x) {
    int bc = blockIdx.x;                 // b*64 + c
    int t  = threadIdx.x;
    const float* base = x + (size_t)bc * 16384;

    int i  = t >> 1;                     // row 0..127
    int j0 = (t & 1) * 64;               // half-row
    const float4* row4 = (const float4*)(base + i * 128 + j0);

    float ca0 = 0.f, ca1 = 0.f, ca2 = 0.f;
#pragma unroll
    for (int k = 0; k < 16; k++) {
        float4 v = row4[k];
        int j = j0 + 4 * k;
        ca0 += v.x + ((j <= 122) ? v.z : 0.f);
        ca1 += v.y + ((j <= 122) ? v.w : 0.f);
        ca2 += ((j >= 2) ? v.x : 0.f) + v.z;
    }
    bool ev = ((i & 1) == 0);
    float f0 = (ev  && i <= 124) ? 1.f : 0.f;
    float f1 = (!ev && i <= 125) ? 1.f : 0.f;
    float f2 = (ev  && i >= 2)   ? 1.f : 0.f;

    float bins[9] = { f0*ca0, f0*ca1, f0*ca2,
                      f1*ca0, f1*ca1, f1*ca2,
                      f2*ca0, f2*ca1, f2*ca2 };
#pragma unroll
    for (int off = 16; off; off >>= 1)
#pragma unroll
        for (int k = 0; k < 9; k++)
            bins[k] += __shfl_down_sync(0xffffffffu, bins[k], off);

    __shared__ float red[8][9];
    int lane = t & 31, w = t >> 5;
    if (lane == 0)
#pragma unroll
        for (int k = 0; k < 9; k++) red[w][k] = bins[k];
    __syncthreads();
    if (t < 9) {
        float s = 0.f;
#pragma unroll
        for (int ww = 0; ww < 8; ww++) s += red[ww][t];
        gS[bc * 9 + t] = s;
    }
}

// =================================================================================
// Kernel 2: condition vector + dynamic weights (tiny GEMMs) + stat zeroing
// =================================================================================
__global__ void __launch_bounds__(256) k_gen(
    const float* __restrict__ cg_w1, const float* __restrict__ cg_b1,
    const float* __restrict__ cg_w2, const float* __restrict__ cg_b2,
    const float* __restrict__ wg_w,  const float* __restrict__ wg_b,
    const float* __restrict__ pg_w,  const float* __restrict__ pg_b,
    const float* __restrict__ bg_w,  const float* __restrict__ bg_b)
{
    __shared__ float Ss[576];
    __shared__ float parts[256];
    __shared__ float c0[16];
    __shared__ float cond[16];

    int b = blockIdx.x;
    int t = threadIdx.x;

    // zero BN stat accumulators (runs before k_main in-stream; deterministic)
    if (b == 0 && t < 64) { gSum[t] = 0.0; gSumSq[t] = 0.0; }

    for (int idx = t; idx < 576; idx += 256) Ss[idx] = gS[b * 576 + idx];
    __syncthreads();

    {
        int co = t >> 4, part = t & 15;
        const float* wrow = cg_w1 + co * 576 + part * 36;
        const float* srow = Ss + part * 36;
        float s = 0.f;
#pragma unroll
        for (int k = 0; k < 36; k++) s += wrow[k] * srow[k];
        parts[t] = s;
    }
    __syncthreads();
    if (t < 16) {
        float s = 0.f;
#pragma unroll
        for (int p = 0; p < 16; p++) s += parts[t * 16 + p];
        s = s * (1.0f / 3969.0f) + cg_b1[t];
        c0[t] = fmaxf(s, 0.f);
    }
    __syncthreads();
    if (t < 16) {
        float s = cg_b2[t];
#pragma unroll
        for (int i = 0; i < 16; i++) s += c0[i] * cg_w2[t * 16 + i];
        cond[t] = fmaxf(s, 0.f);
    }
    __syncthreads();

    for (int r = t; r < 576; r += 256) {
        float s = wg_b[r];
        const float* wr = wg_w + r * 16;
#pragma unroll
        for (int q = 0; q < 16; q++) s += cond[q] * wr[q];
        gDw[b * 576 + r] = fmaxf(s, 0.f);
    }
    // pointwise weights [b][o][c], fp16 for the HMMA path
    for (int r = t; r < 4096; r += 256) {
        float s = pg_b[r];
        const float* wr = pg_w + r * 16;
#pragma unroll
        for (int q = 0; q < 16; q++) s += cond[q] * wr[q];
        gPwH[b * 4096 + r] = __float2half(fmaxf(s, 0.f));
    }
    if (t < 64) {
        float s = bg_b[t];
        const float* wr = bg_w + t * 16;
#pragma unroll
        for (int q = 0; q < 16; q++) s += cond[q] * wr[q];
        gDb[b * 64 + t] = s;
    }
}

// =================================================================================
// Kernel 3: fused depthwise3x3 + fp16 MMA (m16n8k16) pointwise, HS=4 rows per CTA.
//   512 threads; 2 CTAs/SM; grid (32, 32). Writes fp16 pre-BN tensor.
// smem (floats):
//   ysH [4 row][32 c2][136 half2]  offset 0      (17408 fl)  pair-interleaved fp16 y
//   pwH [64 o][72 half]            offset 17408  (2304 fl)
//   dws [64 c][12]                 offset 19712  (768 fl)
//   dbs [64]                       offset 20480
//   sst [128]                      offset 20544  -> 20672 fl = 82688 B
// Depthwise: warp w handles channels [4w,4w+4); loads 6 x-rows/channel,
//   computes 4 output rows; even-channel rows staged as half2, merged via PRMT.
// MMA: warp does 2 tiles: (row = (wid>>3)+2*tile, mt=(wid>>2)&1, nb=wid&3), M32xN32.
// =================================================================================
__global__ void __launch_bounds__(512, 2) k_main(const float* __restrict__ x)
{
    extern __shared__ float sm[];
    char*  ysB = (char*)sm;                       // byte base of ysH
    const uint32_t* pw32 = (const uint32_t*)(sm + 17408);  // pwH as u32 (2 halves)
    float* dws = sm + 19712;
    float* dbs = sm + 20480;
    float* sst = sm + 20544;

    int tid  = threadIdx.x;
    int lane = tid & 31, wid = tid >> 5;
    int h0 = blockIdx.x * 4, b = blockIdx.y;

    // ---- stage per-sample dynamic weights into smem ----
    {
        // pw fp16: 4096 halves = 512 uint4; pad rows to 72 halves (144 B)
        const uint4* src = (const uint4*)(gPwH + b * 4096);
        uint4 v = src[tid];
        int o = tid >> 3, j = tid & 7;
        *(uint4*)((char*)(sm + 17408) + o * 144 + j * 16) = v;

        for (int idx = tid; idx < 576; idx += 512) {
            int c = idx / 9, jj = idx - 9 * c;
            dws[c * 12 + jj] = gDw[b * 576 + idx];
        }
        if (tid < 64) dbs[tid] = gDb[b * 64 + tid];
        else if (tid >= 64 && tid < 192) sst[tid - 64] = 0.f;
    }
    __syncthreads();

    // ---- depthwise 3x3 (pad=1); warp w: channels [4w,4w+4) = 2 pairs; 4 rows ----
    const float4* xb = (const float4*)(x + (size_t)b * 64 * 16384);
    const float4 z4 = make_float4(0.f, 0.f, 0.f, 0.f);

#pragma unroll
    for (int pr = 0; pr < 2; pr++) {
        uint32_t eS[8];                         // even-channel rows, packed half2
        int c2 = wid * 2 + pr;
#pragma unroll
        for (int half = 0; half < 2; half++) {
            int c = wid * 4 + pr * 2 + half;
            const float4* plane = xb + (size_t)c * 4096;
            float4 m[6];
            float lf[6], rg[6];
#pragma unroll
            for (int i = 0; i < 6; i++) {
                int gh = h0 - 1 + i;
                m[i] = ((unsigned)gh < 128u) ? plane[gh * 32 + lane] : z4;
            }
#pragma unroll
            for (int i = 0; i < 6; i++) {
                lf[i] = __shfl_up_sync(0xffffffffu, m[i].w, 1);
                rg[i] = __shfl_down_sync(0xffffffffu, m[i].x, 1);
                if (lane == 0)  lf[i] = 0.f;
                if (lane == 31) rg[i] = 0.f;
            }

            const float* wp = dws + c * 12;
            float4 wA = *(const float4*)(wp);       // w00 w01 w02 w10
            float4 wB = *(const float4*)(wp + 4);   // w11 w12 w20 w21
            float  w8 = wp[8];                      // w22

#pragma unroll
            for (int row = 0; row < 4; row++) {
                float a0 = 0.f, a1 = 0.f, a2 = 0.f, a3 = 0.f;
#pragma unroll
                for (int r = 0; r < 3; r++) {
                    int i = row + r;
                    float w0 = (r == 0) ? wA.x : (r == 1) ? wA.w : wB.z;
                    float w1 = (r == 0) ? wA.y : (r == 1) ? wB.x : wB.w;
                    float w2 = (r == 0) ? wA.z : (r == 1) ? wB.y : w8;
                    a0 += w0 * lf[i]  + w1 * m[i].x + w2 * m[i].y;
                    a1 += w0 * m[i].x + w1 * m[i].y + w2 * m[i].z;
                    a2 += w0 * m[i].y + w1 * m[i].z + w2 * m[i].w;
                    a3 += w0 * m[i].z + w1 * m[i].w + w2 * rg[i];
                }
                __half2 p01 = __floats2half2_rn(a0, a1);
                __half2 p23 = __floats2half2_rn(a2, a3);
                uint32_t u01 = *(uint32_t*)&p01;
                uint32_t u23 = *(uint32_t*)&p23;
                if (half == 0) {
                    eS[2 * row]     = u01;
                    eS[2 * row + 1] = u23;
                } else {
                    // interleave (even, odd) per w: (e0,o0),(e1,o1),(e2,o2),(e3,o3)
                    uint4 v;
                    v.x = __byte_perm(eS[2 * row],     u01, 0x5410);
                    v.y = __byte_perm(eS[2 * row],     u01, 0x7632);
                    v.z = __byte_perm(eS[2 * row + 1], u23, 0x5410);
                    v.w = __byte_perm(eS[2 * row + 1], u23, 0x7632);
                    *(uint4*)(ysB + row * 17408 + c2 * 544 + lane * 16) = v;
                }
            }
        }
    }
    __syncthreads();

    // ---- fp16 MMA pointwise: warp does 2 tiles (rows r, r+2); M32 x N32 each ----
    int mt = (wid >> 2) & 1, nb = wid & 3;
    int ob = mt * 32, wbase = nb * 32;
    int g = lane >> 2, t4 = lane & 3;

#pragma unroll
    for (int tile = 0; tile < 2; tile++) {
        int row = (wid >> 3) + 2 * tile;
        const char* ysr = ysB + row * 17408;

        float acc[2][4][4];
#pragma unroll
        for (int ms = 0; ms < 2; ms++)
#pragma unroll
            for (int n = 0; n < 4; n++)
#pragma unroll
                for (int j = 0; j < 4; j++) acc[ms][n][j] = 0.f;

#pragma unroll
        for (int k = 0; k < 4; k++) {              // K = 16 per step
            uint32_t a[2][4];
#pragma unroll
            for (int ms = 0; ms < 2; ms++) {
                int r0 = (ob + 16 * ms + g) * 36 + 8 * k + t4;   // u32 units, pitch 36
                a[ms][0] = pw32[r0];
                a[ms][2] = pw32[r0 + 4];
                a[ms][1] = pw32[r0 + 8 * 36];
                a[ms][3] = pw32[r0 + 8 * 36 + 4];
            }
            const char* bR = ysr + (8 * k + t4) * 544;
#pragma unroll
            for (int n = 0; n < 4; n++) {
                int col = (wbase + 8 * n + g) * 4;
                uint32_t b0 = *(const uint32_t*)(bR + col);
                uint32_t b1 = *(const uint32_t*)(bR + 4 * 544 + col);
#pragma unroll
                for (int ms = 0; ms < 2; ms++) {
                    asm("mma.sync.aligned.m16n8k16.row.col.f32.f16.f16.f32 "
                        "{%0,%1,%2,%3}, {%4,%5,%6,%7}, {%8,%9}, {%0,%1,%2,%3};"
                        : "+f"(acc[ms][n][0]), "+f"(acc[ms][n][1]),
                          "+f"(acc[ms][n][2]), "+f"(acc[ms][n][3])
                        : "r"(a[ms][0]), "r"(a[ms][1]), "r"(a[ms][2]), "r"(a[ms][3]),
                          "r"(b0), "r"(b1));
                }
            }
        }

        // ---- epilogue: +dbias, store fp16, BN partial stats (fp32) ----
        __half* outb = gOut16 + (size_t)(b * 64) * 16384 + (size_t)(h0 + row) * 128;
        float sAcc[2][2], s2Acc[2][2];
#pragma unroll
        for (int ms = 0; ms < 2; ms++) {
            sAcc[ms][0] = 0.f; sAcc[ms][1] = 0.f;
            s2Acc[ms][0] = 0.f; s2Acc[ms][1] = 0.f;
        }

#pragma unroll
        for (int ms = 0; ms < 2; ms++) {
            int rLo = ob + 16 * ms + g;
            float dbLo = dbs[rLo], dbHi = dbs[rLo + 8];
            size_t oLo = (size_t)rLo * 16384;
            size_t oHi = (size_t)(rLo + 8) * 16384;
#pragma unroll
            for (int n = 0; n < 4; n++) {
                int w = wbase + 8 * n + 2 * t4;
                float v0 = acc[ms][n][0] + dbLo;
                float v1 = acc[ms][n][1] + dbLo;
                float v2 = acc[ms][n][2] + dbHi;
                float v3 = acc[ms][n][3] + dbHi;
                *(__half2*)(outb + oLo + w) = __floats2half2_rn(v0, v1);
                *(__half2*)(outb + oHi + w) = __floats2half2_rn(v2, v3);
                sAcc[ms][0]  += v0 + v1;            s2Acc[ms][0] += v0 * v0 + v1 * v1;
                sAcc[ms][1]  += v2 + v3;            s2Acc[ms][1] += v2 * v2 + v3 * v3;
            }
        }
#pragma unroll
        for (int off = 1; off <= 2; off <<= 1)
#pragma unroll
            for (int ms = 0; ms < 2; ms++)
#pragma unroll
                for (int hl = 0; hl < 2; hl++) {
                    sAcc[ms][hl]  += __shfl_xor_sync(0xffffffffu, sAcc[ms][hl],  off);
                    s2Acc[ms][hl] += __shfl_xor_sync(0xffffffffu, s2Acc[ms][hl], off);
                }
        if (t4 == 0) {
#pragma unroll
            for (int ms = 0; ms < 2; ms++)
#pragma unroll
                for (int hl = 0; hl < 2; hl++) {
                    int o = ob + 16 * ms + 8 * hl + g;
                    atomicAdd(&sst[o],      sAcc[ms][hl]);
                    atomicAdd(&sst[64 + o], s2Acc[ms][hl]);
                }
        }
    }

    __syncthreads();
    if (tid < 64)       atomicAdd(&gSum[tid],        (double)sst[tid]);
    else if (tid < 128) atomicAdd(&gSumSq[tid - 64], (double)sst[tid]);
}

// =================================================================================
// Kernel 4: BN finalize (per-block, from global stats) + apply
//   reads fp16 scratch (streaming), writes f32 out (streaming); MLP=8
// =================================================================================
__global__ void __launch_bounds__(256) k_bn(float* __restrict__ out,
                                            const float* __restrict__ gamma,
                                            const float* __restrict__ beta)
{
    __shared__ float scS[64], shS[64];
    int t = threadIdx.x;
    if (t < 64) {
        const double n = 524288.0;   // 32 * 128 * 128
        double mean = gSum[t] / n;
        double var  = gSumSq[t] / n - mean * mean;
        double inv  = 1.0 / sqrt(var + 1e-5);
        double gg   = (double)gamma[t];
        scS[t] = (float)(gg * inv);
        shS[t] = (float)((double)beta[t] - mean * gg * inv);
    }
    __syncthreads();

    int base = blockIdx.x * 2048 + threadIdx.x;
    const uint2* src = (const uint2*)gOut16;     // 4 halves per uint2 == 1 float4 slot
    uint2 raw[8];
#pragma unroll
    for (int j = 0; j < 8; j++) raw[j] = __ldcs(src + base + 256 * j);
#pragma unroll
    for (int j = 0; j < 8; j++) {
        int idx = base + 256 * j;
        __half2 hA = *(__half2*)&raw[j].x;
        __half2 hB = *(__half2*)&raw[j].y;
        float2 fA = __half22float2(hA);
        float2 fB = __half22float2(hB);
        int o = (idx >> 12) & 63;                // 4096 float4 per (b,o) plane
        float sc = scS[o], sh = shS[o];
        float4 v;
        v.x = fmaf(fA.x, sc, sh);
        v.y = fmaf(fA.y, sc, sh);
        v.z = fmaf(fB.x, sc, sh);
        v.w = fmaf(fB.y, sc, sh);
        __stcs((float4*)out + idx, v);
    }
}

// =================================================================================
extern "C" void kernel_launch(void* const* d_in, const int* in_sizes, int n_in,
                              void* d_out, int out_size)
{
    const float* x      = (const float*)d_in[0];
    const float* cg_w1  = (const float*)d_in[1];
    const float* cg_b1  = (const float*)d_in[2];
    const float* cg_w2  = (const float*)d_in[3];
    const float* cg_b2  = (const float*)d_in[4];
    const float* wg_w   = (const float*)d_in[5];
    const float* wg_b   = (const float*)d_in[6];
    const float* pg_w   = (const float*)d_in[7];
    const float* pg_b   = (const float*)d_in[8];
    const float* bg_w   = (const float*)d_in[9];
    const float* bg_b   = (const float*)d_in[10];
    const float* bn_g   = (const float*)d_in[11];
    const float* bn_b   = (const float*)d_in[12];
    float* out = (float*)d_out;

    cudaFuncSetAttribute(k_main, cudaFuncAttributeMaxDynamicSharedMemorySize, 82688);

    k_cond_sums<<<2048, 256>>>(x);
    k_gen<<<32, 256>>>(cg_w1, cg_b1, cg_w2, cg_b2, wg_w, wg_b, pg_w, pg_b, bg_w, bg_b);
    dim3 g3(32, 32);
    k_main<<<g3, 512, 82688>>>(x);
    k_bn<<<4096, 256>>>(out, bn_g, bn_b);
}

// round 15
// speedup vs baseline: 1.2017x; 1.0413x over previous
#include <cuda_runtime.h>
#include <cuda_fp16.h>
#include <cstdint>

typedef unsigned long long ull;

// ---------------- device scratch (no runtime allocation allowed) ----------------
__device__ float  gS[32 * 64 * 9];     // strided sums for cond conv
__device__ float  gDw[32 * 576];       // per-sample depthwise weights (fp32)
__device__ __half gPwH[32 * 4096];     // per-sample pointwise weights [b][o][c], fp16
__device__ float  gDb[32 * 64];        // per-sample dynamic bias
__device__ double gSum[64], gSumSq[64];// BN statistics accumulators
__device__ __half gOut16[32 * 64 * 16384];   // pre-BN intermediate (fp16, 67 MB)

// =================================================================================
// Kernel 1: per-(b,c) 9 strided sums, COALESCED: warp w owns rows [16w, 16w+16),
//   lane l loads float4 (row, 4l). 4 lines per LDG instead of 32.
// =================================================================================
__global__ void __launch_bounds__(256) k_cond_sums(const float* __restrict__ x) {
    int bc = blockIdx.x;                 // b*64 + c
    int t  = threadIdx.x;
    int lane = t & 31, w = t >> 5;
    const float4* p = (const float4*)(x + (size_t)bc * 16384);

    float bins[9] = {0.f,0.f,0.f,0.f,0.f,0.f,0.f,0.f,0.f};
    // column-class lane masks (col of v.x = 4*lane):
    //   kw=0: v.x always (col<=124 ok), v.z if lane<=30 (col 4l+2<=124)
    //   kw=1: v.y always (odd col<=125), v.w if lane<=30 (col 4l+3<=125)
    //   kw=2: v.x if lane>=1 (col>=2), v.z always
    float mzw = (lane <= 30) ? 1.f : 0.f;
    float mx2 = (lane >= 1)  ? 1.f : 0.f;

#pragma unroll
    for (int r = 0; r < 16; r++) {
        int i = w * 16 + r;
        float4 v = p[i * 32 + lane];
        float ca0 = v.x + mzw * v.z;
        float ca1 = v.y + mzw * v.w;
        float ca2 = mx2 * v.x + v.z;
        bool ev = ((i & 1) == 0);
        float f0 = (ev  && i <= 124) ? 1.f : 0.f;
        float f1 = (!ev && i <= 125) ? 1.f : 0.f;
        float f2 = (ev  && i >= 2)   ? 1.f : 0.f;
        bins[0] += f0 * ca0;  bins[1] += f0 * ca1;  bins[2] += f0 * ca2;
        bins[3] += f1 * ca0;  bins[4] += f1 * ca1;  bins[5] += f1 * ca2;
        bins[6] += f2 * ca0;  bins[7] += f2 * ca1;  bins[8] += f2 * ca2;
    }

#pragma unroll
    for (int off = 16; off; off >>= 1)
#pragma unroll
        for (int k = 0; k < 9; k++)
            bins[k] += __shfl_down_sync(0xffffffffu, bins[k], off);

    __shared__ float red[8][9];
    if (lane == 0)
#pragma unroll
        for (int k = 0; k < 9; k++) red[w][k] = bins[k];
    __syncthreads();
    if (t < 9) {
        float s = 0.f;
#pragma unroll
        for (int ww = 0; ww < 8; ww++) s += red[ww][t];
        gS[bc * 9 + t] = s;
    }
}

// =================================================================================
// Kernel 2: condition vector + dynamic weights (tiny GEMMs) + stat zeroing
// =================================================================================
__global__ void __launch_bounds__(256) k_gen(
    const float* __restrict__ cg_w1, const float* __restrict__ cg_b1,
    const float* __restrict__ cg_w2, const float* __restrict__ cg_b2,
    const float* __restrict__ wg_w,  const float* __restrict__ wg_b,
    const float* __restrict__ pg_w,  const float* __restrict__ pg_b,
    const float* __restrict__ bg_w,  const float* __restrict__ bg_b)
{
    __shared__ float Ss[576];
    __shared__ float parts[256];
    __shared__ float c0[16];
    __shared__ float cond[16];

    int b = blockIdx.x;
    int t = threadIdx.x;

    // zero BN stat accumulators (runs before k_main in-stream; deterministic)
    if (b == 0 && t < 64) { gSum[t] = 0.0; gSumSq[t] = 0.0; }

    for (int idx = t; idx < 576; idx += 256) Ss[idx] = gS[b * 576 + idx];
    __syncthreads();

    {
        int co = t >> 4, part = t & 15;
        const float* wrow = cg_w1 + co * 576 + part * 36;
        const float* srow = Ss + part * 36;
        float s = 0.f;
#pragma unroll
        for (int k = 0; k < 36; k++) s += wrow[k] * srow[k];
        parts[t] = s;
    }
    __syncthreads();
    if (t < 16) {
        float s = 0.f;
#pragma unroll
        for (int p = 0; p < 16; p++) s += parts[t * 16 + p];
        s = s * (1.0f / 3969.0f) + cg_b1[t];
        c0[t] = fmaxf(s, 0.f);
    }
    __syncthreads();
    if (t < 16) {
        float s = cg_b2[t];
#pragma unroll
        for (int i = 0; i < 16; i++) s += c0[i] * cg_w2[t * 16 + i];
        cond[t] = fmaxf(s, 0.f);
    }
    __syncthreads();

    for (int r = t; r < 576; r += 256) {
        float s = wg_b[r];
        const float* wr = wg_w + r * 16;
#pragma unroll
        for (int q = 0; q < 16; q++) s += cond[q] * wr[q];
        gDw[b * 576 + r] = fmaxf(s, 0.f);
    }
    // pointwise weights [b][o][c], fp16 for the HMMA path
    for (int r = t; r < 4096; r += 256) {
        float s = pg_b[r];
        const float* wr = pg_w + r * 16;
#pragma unroll
        for (int q = 0; q < 16; q++) s += cond[q] * wr[q];
        gPwH[b * 4096 + r] = __float2half(fmaxf(s, 0.f));
    }
    if (t < 64) {
        float s = bg_b[t];
        const float* wr = bg_w + t * 16;
#pragma unroll
        for (int q = 0; q < 16; q++) s += cond[q] * wr[q];
        gDb[b * 64 + t] = s;
    }
}

// =================================================================================
// Kernel 3: fused depthwise3x3 + fp16 MMA (m16n8k16) pointwise, HS=2 rows per CTA.
//   512 threads; 2 CTAs/SM; grid (64, 32). Writes fp16 pre-BN tensor.  [R12 proven]
// smem (floats):
//   ysH [2 row][32 c2][136 half2]  offset 0     (8704 fl)   pair-interleaved fp16 y
//   pwH [64 o][72 half]            offset 8704  (2304 fl)
//   dws [64 c][12]                 offset 11008 (768 fl)
//   dbs [64]                       offset 11776
//   sst [128]                      offset 11840  -> 11968 fl = 47872 B
// =================================================================================
__global__ void __launch_bounds__(512, 2) k_main(const float* __restrict__ x)
{
    extern __shared__ float sm[];
    char*  ysB = (char*)sm;                       // byte base of ysH
    const uint32_t* pw32 = (const uint32_t*)(sm + 8704);  // pwH as u32 (2 halves)
    float* dws = sm + 11008;
    float* dbs = sm + 11776;
    float* sst = sm + 11840;

    int tid  = threadIdx.x;
    int lane = tid & 31, wid = tid >> 5;
    int h0 = blockIdx.x * 2, b = blockIdx.y;

    // ---- stage per-sample dynamic weights into smem ----
    {
        // pw fp16: 4096 halves = 512 uint4; pad rows to 72 halves (144 B)
        const uint4* src = (const uint4*)(gPwH + b * 4096);
        uint4 v = src[tid];
        int o = tid >> 3, j = tid & 7;
        *(uint4*)((char*)(sm + 8704) + o * 144 + j * 16) = v;

        for (int idx = tid; idx < 576; idx += 512) {
            int c = idx / 9, jj = idx - 9 * c;
            dws[c * 12 + jj] = gDw[b * 576 + idx];
        }
        if (tid < 64) dbs[tid] = gDb[b * 64 + tid];
        else if (tid >= 64 && tid < 192) sst[tid - 64] = 0.f;
    }
    __syncthreads();

    // ---- depthwise 3x3 (pad=1); warp w: channels [4w,4w+4) = 2 pairs; 2 rows ----
    const float4* xb = (const float4*)(x + (size_t)b * 64 * 16384);
    const float4 z4 = make_float4(0.f, 0.f, 0.f, 0.f);
    bool hasT = (h0 >= 1), hasB = (h0 <= 125);

#pragma unroll
    for (int pr = 0; pr < 2; pr++) {
        float rE[2][4], rO[2][4];
#pragma unroll
        for (int half = 0; half < 2; half++) {
            int c = wid * 4 + pr * 2 + half;
            const float4* plane = xb + (size_t)c * 4096;
            float4 m[4];
            m[0] = hasT ? plane[(h0 - 1) * 32 + lane] : z4;
            m[1] =        plane[h0       * 32 + lane];
            m[2] =        plane[(h0 + 1) * 32 + lane];
            m[3] = hasB ? plane[(h0 + 2) * 32 + lane] : z4;

            float lf[4], rg[4];
#pragma unroll
            for (int i = 0; i < 4; i++) {
                lf[i] = __shfl_up_sync(0xffffffffu, m[i].w, 1);
                rg[i] = __shfl_down_sync(0xffffffffu, m[i].x, 1);
                if (lane == 0)  lf[i] = 0.f;
                if (lane == 31) rg[i] = 0.f;
            }

            const float* wp = dws + c * 12;
            float4 wA = *(const float4*)(wp);       // w00 w01 w02 w10
            float4 wB = *(const float4*)(wp + 4);   // w11 w12 w20 w21
            float  w8 = wp[8];                      // w22

#pragma unroll
            for (int row = 0; row < 2; row++) {
                float a0 = 0.f, a1 = 0.f, a2 = 0.f, a3 = 0.f;
#pragma unroll
                for (int r = 0; r < 3; r++) {
                    int i = row + r;
                    float w0 = (r == 0) ? wA.x : (r == 1) ? wA.w : wB.z;
                    float w1 = (r == 0) ? wA.y : (r == 1) ? wB.x : wB.w;
                    float w2 = (r == 0) ? wA.z : (r == 1) ? wB.y : w8;
                    a0 += w0 * lf[i]  + w1 * m[i].x + w2 * m[i].y;
                    a1 += w0 * m[i].x + w1 * m[i].y + w2 * m[i].z;
                    a2 += w0 * m[i].y + w1 * m[i].z + w2 * m[i].w;
                    a3 += w0 * m[i].z + w1 * m[i].w + w2 * rg[i];
                }
                float* dst = half ? rO[row] : rE[row];
                dst[0] = a0; dst[1] = a1; dst[2] = a2; dst[3] = a3;
            }
        }
        // pack channel pair -> half2 (low = even channel = lower k) and store
        int c2 = wid * 2 + pr;
#pragma unroll
        for (int row = 0; row < 2; row++) {
            __half2 h0p = __floats2half2_rn(rE[row][0], rO[row][0]);
            __half2 h1p = __floats2half2_rn(rE[row][1], rO[row][1]);
            __half2 h2p = __floats2half2_rn(rE[row][2], rO[row][2]);
            __half2 h3p = __floats2half2_rn(rE[row][3], rO[row][3]);
            uint4 v;
            v.x = *(uint32_t*)&h0p; v.y = *(uint32_t*)&h1p;
            v.z = *(uint32_t*)&h2p; v.w = *(uint32_t*)&h3p;
            *(uint4*)(ysB + row * 17408 + c2 * 544 + lane * 16) = v;
        }
    }
    __syncthreads();

    // ---- fp16 MMA pointwise: warp -> (row, mt, nb); M32 x N32 tile ----
    int row = wid >> 3, mt = (wid >> 2) & 1, nb = wid & 3;
    int ob = mt * 32, wbase = nb * 32;
    int g = lane >> 2, t4 = lane & 3;
    const char* ysr = ysB + row * 17408;

    float acc[2][4][4];
#pragma unroll
    for (int ms = 0; ms < 2; ms++)
#pragma unroll
        for (int n = 0; n < 4; n++)
#pragma unroll
            for (int j = 0; j < 4; j++) acc[ms][n][j] = 0.f;

#pragma unroll
    for (int k = 0; k < 4; k++) {              // K = 16 per step
        uint32_t a[2][4];
#pragma unroll
        for (int ms = 0; ms < 2; ms++) {
            int r0 = (ob + 16 * ms + g) * 36 + 8 * k + t4;   // u32 units, pitch 36
            a[ms][0] = pw32[r0];
            a[ms][2] = pw32[r0 + 4];
            a[ms][1] = pw32[r0 + 8 * 36];
            a[ms][3] = pw32[r0 + 8 * 36 + 4];
        }
        const char* bR = ysr + (8 * k + t4) * 544;
#pragma unroll
        for (int n = 0; n < 4; n++) {
            int col = (wbase + 8 * n + g) * 4;
            uint32_t b0 = *(const uint32_t*)(bR + col);
            uint32_t b1 = *(const uint32_t*)(bR + 4 * 544 + col);
#pragma unroll
            for (int ms = 0; ms < 2; ms++) {
                asm("mma.sync.aligned.m16n8k16.row.col.f32.f16.f16.f32 "
                    "{%0,%1,%2,%3}, {%4,%5,%6,%7}, {%8,%9}, {%0,%1,%2,%3};"
                    : "+f"(acc[ms][n][0]), "+f"(acc[ms][n][1]),
                      "+f"(acc[ms][n][2]), "+f"(acc[ms][n][3])
                    : "r"(a[ms][0]), "r"(a[ms][1]), "r"(a[ms][2]), "r"(a[ms][3]),
                      "r"(b0), "r"(b1));
            }
        }
    }

    // ---- epilogue: +dbias, store fp16, BN partial stats (fp32) ----
    __half* outb = gOut16 + (size_t)(b * 64) * 16384 + (size_t)(h0 + row) * 128;
    float sAcc[2][2], s2Acc[2][2];
#pragma unroll
    for (int ms = 0; ms < 2; ms++) {
        sAcc[ms][0] = 0.f; sAcc[ms][1] = 0.f;
        s2Acc[ms][0] = 0.f; s2Acc[ms][1] = 0.f;
    }

#pragma unroll
    for (int ms = 0; ms < 2; ms++) {
        int rLo = ob + 16 * ms + g;
        float dbLo = dbs[rLo], dbHi = dbs[rLo + 8];
        size_t oLo = (size_t)rLo * 16384;
        size_t oHi = (size_t)(rLo + 8) * 16384;
#pragma unroll
        for (int n = 0; n < 4; n++) {
            int w = wbase + 8 * n + 2 * t4;
            float v0 = acc[ms][n][0] + dbLo;
            float v1 = acc[ms][n][1] + dbLo;
            float v2 = acc[ms][n][2] + dbHi;
            float v3 = acc[ms][n][3] + dbHi;
            *(__half2*)(outb + oLo + w) = __floats2half2_rn(v0, v1);
            *(__half2*)(outb + oHi + w) = __floats2half2_rn(v2, v3);
            sAcc[ms][0]  += v0 + v1;            s2Acc[ms][0] += v0 * v0 + v1 * v1;
            sAcc[ms][1]  += v2 + v3;            s2Acc[ms][1] += v2 * v2 + v3 * v3;
        }
    }
#pragma unroll
    for (int off = 1; off <= 2; off <<= 1)
#pragma unroll
        for (int ms = 0; ms < 2; ms++)
#pragma unroll
            for (int hl = 0; hl < 2; hl++) {
                sAcc[ms][hl]  += __shfl_xor_sync(0xffffffffu, sAcc[ms][hl],  off);
                s2Acc[ms][hl] += __shfl_xor_sync(0xffffffffu, s2Acc[ms][hl], off);
            }
    if (t4 == 0) {
#pragma unroll
        for (int ms = 0; ms < 2; ms++)
#pragma unroll
            for (int hl = 0; hl < 2; hl++) {
                int o = ob + 16 * ms + 8 * hl + g;
                atomicAdd(&sst[o],      sAcc[ms][hl]);
                atomicAdd(&sst[64 + o], s2Acc[ms][hl]);
            }
    }

    __syncthreads();
    if (tid < 64)       atomicAdd(&gSum[tid],        (double)sst[tid]);
    else if (tid < 128) atomicAdd(&gSumSq[tid - 64], (double)sst[tid]);
}

// =================================================================================
// Kernel 4: BN finalize (per-block, from global stats) + apply
//   reads fp16 scratch (uint4 streaming loads), writes f32 out (streaming)
// =================================================================================
__global__ void __launch_bounds__(256) k_bn(float* __restrict__ out,
                                            const float* __restrict__ gamma,
                                            const float* __restrict__ beta)
{
    __shared__ float scS[64], shS[64];
    int t = threadIdx.x;
    if (t < 64) {
        const double n = 524288.0;   // 32 * 128 * 128
        double mean = gSum[t] / n;
        double var  = gSumSq[t] / n - mean * mean;
        double inv  = 1.0 / sqrt(var + 1e-5);
        double gg   = (double)gamma[t];
        scS[t] = (float)(gg * inv);
        shS[t] = (float)((double)beta[t] - mean * gg * inv);
    }
    __syncthreads();

    int base = blockIdx.x * 1024 + threadIdx.x;  // uint4 index (8 halves each)
    const uint4* src = (const uint4*)gOut16;
    uint4 raw[4];
#pragma unroll
    for (int j = 0; j < 4; j++) raw[j] = __ldcs(src + base + 256 * j);
#pragma unroll
    for (int j = 0; j < 4; j++) {
        int idx4 = base + 256 * j;
        int fidx = idx4 * 2;                     // first float4-out index
        int o = (fidx >> 12) & 63;               // 4096 float4 per (b,o) plane
        float sc = scS[o], sh = shS[o];

        __half2 hA = *(__half2*)&raw[j].x;
        __half2 hB = *(__half2*)&raw[j].y;
        __half2 hC = *(__half2*)&raw[j].z;
        __half2 hD = *(__half2*)&raw[j].w;
        float2 fA = __half22float2(hA);
        float2 fB = __half22float2(hB);
        float2 fC = __half22float2(hC);
        float2 fD = __half22float2(hD);

        float4 v0, v1;
        v0.x = fmaf(fA.x, sc, sh);  v0.y = fmaf(fA.y, sc, sh);
        v0.z = fmaf(fB.x, sc, sh);  v0.w = fmaf(fB.y, sc, sh);
        v1.x = fmaf(fC.x, sc, sh);  v1.y = fmaf(fC.y, sc, sh);
        v1.z = fmaf(fD.x, sc, sh);  v1.w = fmaf(fD.y, sc, sh);
        __stcs((float4*)out + fidx,     v0);
        __stcs((float4*)out + fidx + 1, v1);
    }
}

// =================================================================================
extern "C" void kernel_launch(void* const* d_in, const int* in_sizes, int n_in,
                              void* d_out, int out_size)
{
    const float* x      = (const float*)d_in[0];
    const float* cg_w1  = (const float*)d_in[1];
    const float* cg_b1  = (const float*)d_in[2];
    const float* cg_w2  = (const float*)d_in[3];
    const float* cg_b2  = (const float*)d_in[4];
    const float* wg_w   = (const float*)d_in[5];
    const float* wg_b   = (const float*)d_in[6];
    const float* pg_w   = (const float*)d_in[7];
    const float* pg_b   = (const float*)d_in[8];
    const float* bg_w   = (const float*)d_in[9];
    const float* bg_b   = (const float*)d_in[10];
    const float* bn_g   = (const float*)d_in[11];
    const float* bn_b   = (const float*)d_in[12];
    float* out = (float*)d_out;

    cudaFuncSetAttribute(k_main, cudaFuncAttributeMaxDynamicSharedMemorySize, 47872);

    k_cond_sums<<<2048, 256>>>(x);
    k_gen<<<32, 256>>>(cg_w1, cg_b1, cg_w2, cg_b2, wg_w, wg_b, pg_w, pg_b, bg_w, bg_b);
    dim3 g3(64, 32);
    k_main<<<g3, 512, 47872>>>(x);
    k_bn<<<4096, 256>>>(out, bn_g, bn_b);
}

// round 16
// speedup vs baseline: 1.2857x; 1.0699x over previous
#include <cuda_runtime.h>
#include <cuda_fp16.h>
#include <cstdint>

typedef unsigned long long ull;

// ---------------- device scratch (no runtime allocation allowed) ----------------
__device__ float  gS[32 * 64 * 9];     // strided sums for cond conv
__device__ float  gDw[32 * 576];       // per-sample depthwise weights (fp32)
__device__ __half gPwH[32 * 4096];     // per-sample pointwise weights [b][o][c], fp16
__device__ float  gDb[32 * 64];        // per-sample dynamic bias
__device__ double gSum[64], gSumSq[64];// BN statistics accumulators
__device__ __half gOut16[32 * 64 * 16384];   // pre-BN intermediate (fp16, 67 MB)

// =================================================================================
// Kernel 1: per-(b,c) 9 strided sums, COALESCED: warp w owns rows [16w, 16w+16),
//   lane l loads float4 (row, 4l). 4 lines per LDG instead of 32.
// =================================================================================
__global__ void __launch_bounds__(256) k_cond_sums(const float* __restrict__ x) {
    int bc = blockIdx.x;                 // b*64 + c
    int t  = threadIdx.x;
    int lane = t & 31, w = t >> 5;
    const float4* p = (const float4*)(x + (size_t)bc * 16384);

    float bins[9] = {0.f,0.f,0.f,0.f,0.f,0.f,0.f,0.f,0.f};
    float mzw = (lane <= 30) ? 1.f : 0.f;
    float mx2 = (lane >= 1)  ? 1.f : 0.f;

#pragma unroll
    for (int r = 0; r < 16; r++) {
        int i = w * 16 + r;
        float4 v = p[i * 32 + lane];
        float ca0 = v.x + mzw * v.z;
        float ca1 = v.y + mzw * v.w;
        float ca2 = mx2 * v.x + v.z;
        bool ev = ((i & 1) == 0);
        float f0 = (ev  && i <= 124) ? 1.f : 0.f;
        float f1 = (!ev && i <= 125) ? 1.f : 0.f;
        float f2 = (ev  && i >= 2)   ? 1.f : 0.f;
        bins[0] += f0 * ca0;  bins[1] += f0 * ca1;  bins[2] += f0 * ca2;
        bins[3] += f1 * ca0;  bins[4] += f1 * ca1;  bins[5] += f1 * ca2;
        bins[6] += f2 * ca0;  bins[7] += f2 * ca1;  bins[8] += f2 * ca2;
    }

#pragma unroll
    for (int off = 16; off; off >>= 1)
#pragma unroll
        for (int k = 0; k < 9; k++)
            bins[k] += __shfl_down_sync(0xffffffffu, bins[k], off);

    __shared__ float red[8][9];
    if (lane == 0)
#pragma unroll
        for (int k = 0; k < 9; k++) red[w][k] = bins[k];
    __syncthreads();
    if (t < 9) {
        float s = 0.f;
#pragma unroll
        for (int ww = 0; ww < 8; ww++) s += red[ww][t];
        gS[bc * 9 + t] = s;
    }
}

// =================================================================================
// Kernel 2: condition vector + dynamic weights (tiny GEMMs) + stat zeroing
// =================================================================================
__global__ void __launch_bounds__(256) k_gen(
    const float* __restrict__ cg_w1, const float* __restrict__ cg_b1,
    const float* __restrict__ cg_w2, const float* __restrict__ cg_b2,
    const float* __restrict__ wg_w,  const float* __restrict__ wg_b,
    const float* __restrict__ pg_w,  const float* __restrict__ pg_b,
    const float* __restrict__ bg_w,  const float* __restrict__ bg_b)
{
    __shared__ float Ss[576];
    __shared__ float parts[256];
    __shared__ float c0[16];
    __shared__ float cond[16];

    int b = blockIdx.x;
    int t = threadIdx.x;

    // zero BN stat accumulators (runs before k_main in-stream; deterministic)
    if (b == 0 && t < 64) { gSum[t] = 0.0; gSumSq[t] = 0.0; }

    for (int idx = t; idx < 576; idx += 256) Ss[idx] = gS[b * 576 + idx];
    __syncthreads();

    {
        int co = t >> 4, part = t & 15;
        const float* wrow = cg_w1 + co * 576 + part * 36;
        const float* srow = Ss + part * 36;
        float s = 0.f;
#pragma unroll
        for (int k = 0; k < 36; k++) s += wrow[k] * srow[k];
        parts[t] = s;
    }
    __syncthreads();
    if (t < 16) {
        float s = 0.f;
#pragma unroll
        for (int p = 0; p < 16; p++) s += parts[t * 16 + p];
        s = s * (1.0f / 3969.0f) + cg_b1[t];
        c0[t] = fmaxf(s, 0.f);
    }
    __syncthreads();
    if (t < 16) {
        float s = cg_b2[t];
#pragma unroll
        for (int i = 0; i < 16; i++) s += c0[i] * cg_w2[t * 16 + i];
        cond[t] = fmaxf(s, 0.f);
    }
    __syncthreads();

    for (int r = t; r < 576; r += 256) {
        float s = wg_b[r];
        const float* wr = wg_w + r * 16;
#pragma unroll
        for (int q = 0; q < 16; q++) s += cond[q] * wr[q];
        gDw[b * 576 + r] = fmaxf(s, 0.f);
    }
    // pointwise weights [b][o][c], fp16 for the HMMA path
    for (int r = t; r < 4096; r += 256) {
        float s = pg_b[r];
        const float* wr = pg_w + r * 16;
#pragma unroll
        for (int q = 0; q < 16; q++) s += cond[q] * wr[q];
        gPwH[b * 4096 + r] = __float2half(fmaxf(s, 0.f));
    }
    if (t < 64) {
        float s = bg_b[t];
        const float* wr = bg_w + t * 16;
#pragma unroll
        for (int q = 0; q < 16; q++) s += cond[q] * wr[q];
        gDb[b * 64 + t] = s;
    }
}

// =================================================================================
// Kernel 3: fused depthwise3x3 + fp16 MMA (m16n8k16) pointwise, HS=2 rows per CTA.
//   512 threads; 2 CTAs/SM; grid (64, 32). Writes fp16 pre-BN tensor.  [R12 proven]
// smem (floats):
//   ysH [2 row][32 c2][136 half2]  offset 0     (8704 fl)   pair-interleaved fp16 y
//   pwH [64 o][72 half]            offset 8704  (2304 fl)
//   dws [64 c][12]                 offset 11008 (768 fl)
//   dbs [64]                       offset 11776
//   sst [128]                      offset 11840  -> 11968 fl = 47872 B
// =================================================================================
__global__ void __launch_bounds__(512, 2) k_main(const float* __restrict__ x)
{
    extern __shared__ float sm[];
    char*  ysB = (char*)sm;                       // byte base of ysH
    const uint32_t* pw32 = (const uint32_t*)(sm + 8704);  // pwH as u32 (2 halves)
    float* dws = sm + 11008;
    float* dbs = sm + 11776;
    float* sst = sm + 11840;

    int tid  = threadIdx.x;
    int lane = tid & 31, wid = tid >> 5;
    int h0 = blockIdx.x * 2, b = blockIdx.y;

    // ---- stage per-sample dynamic weights into smem ----
    {
        // pw fp16: 4096 halves = 512 uint4; pad rows to 72 halves (144 B)
        const uint4* src = (const uint4*)(gPwH + b * 4096);
        uint4 v = src[tid];
        int o = tid >> 3, j = tid & 7;
        *(uint4*)((char*)(sm + 8704) + o * 144 + j * 16) = v;

        for (int idx = tid; idx < 576; idx += 512) {
            int c = idx / 9, jj = idx - 9 * c;
            dws[c * 12 + jj] = gDw[b * 576 + idx];
        }
        if (tid < 64) dbs[tid] = gDb[b * 64 + tid];
        else if (tid >= 64 && tid < 192) sst[tid - 64] = 0.f;
    }
    __syncthreads();

    // ---- depthwise 3x3 (pad=1); warp w: channels [4w,4w+4) = 2 pairs; 2 rows ----
    const float4* xb = (const float4*)(x + (size_t)b * 64 * 16384);
    const float4 z4 = make_float4(0.f, 0.f, 0.f, 0.f);
    bool hasT = (h0 >= 1), hasB = (h0 <= 125);

#pragma unroll
    for (int pr = 0; pr < 2; pr++) {
        float rE[2][4], rO[2][4];
#pragma unroll
        for (int half = 0; half < 2; half++) {
            int c = wid * 4 + pr * 2 + half;
            const float4* plane = xb + (size_t)c * 4096;
            float4 m[4];
            m[0] = hasT ? plane[(h0 - 1) * 32 + lane] : z4;
            m[1] =        plane[h0       * 32 + lane];
            m[2] =        plane[(h0 + 1) * 32 + lane];
            m[3] = hasB ? plane[(h0 + 2) * 32 + lane] : z4;

            float lf[4], rg[4];
#pragma unroll
            for (int i = 0; i < 4; i++) {
                lf[i] = __shfl_up_sync(0xffffffffu, m[i].w, 1);
                rg[i] = __shfl_down_sync(0xffffffffu, m[i].x, 1);
                if (lane == 0)  lf[i] = 0.f;
                if (lane == 31) rg[i] = 0.f;
            }

            const float* wp = dws + c * 12;
            float4 wA = *(const float4*)(wp);       // w00 w01 w02 w10
            float4 wB = *(const float4*)(wp + 4);   // w11 w12 w20 w21
            float  w8 = wp[8];                      // w22

#pragma unroll
            for (int row = 0; row < 2; row++) {
                float a0 = 0.f, a1 = 0.f, a2 = 0.f, a3 = 0.f;
#pragma unroll
                for (int r = 0; r < 3; r++) {
                    int i = row + r;
                    float w0 = (r == 0) ? wA.x : (r == 1) ? wA.w : wB.z;
                    float w1 = (r == 0) ? wA.y : (r == 1) ? wB.x : wB.w;
                    float w2 = (r == 0) ? wA.z : (r == 1) ? wB.y : w8;
                    a0 += w0 * lf[i]  + w1 * m[i].x + w2 * m[i].y;
                    a1 += w0 * m[i].x + w1 * m[i].y + w2 * m[i].z;
                    a2 += w0 * m[i].y + w1 * m[i].z + w2 * m[i].w;
                    a3 += w0 * m[i].z + w1 * m[i].w + w2 * rg[i];
                }
                float* dst = half ? rO[row] : rE[row];
                dst[0] = a0; dst[1] = a1; dst[2] = a2; dst[3] = a3;
            }
        }
        // pack channel pair -> half2 (low = even channel = lower k) and store
        int c2 = wid * 2 + pr;
#pragma unroll
        for (int row = 0; row < 2; row++) {
            __half2 h0p = __floats2half2_rn(rE[row][0], rO[row][0]);
            __half2 h1p = __floats2half2_rn(rE[row][1], rO[row][1]);
            __half2 h2p = __floats2half2_rn(rE[row][2], rO[row][2]);
            __half2 h3p = __floats2half2_rn(rE[row][3], rO[row][3]);
            uint4 v;
            v.x = *(uint32_t*)&h0p; v.y = *(uint32_t*)&h1p;
            v.z = *(uint32_t*)&h2p; v.w = *(uint32_t*)&h3p;
            *(uint4*)(ysB + row * 17408 + c2 * 544 + lane * 16) = v;
        }
    }
    __syncthreads();

    // ---- fp16 MMA pointwise: warp -> (row, mt, nb); M32 x N32 tile ----
    int row = wid >> 3, mt = (wid >> 2) & 1, nb = wid & 3;
    int ob = mt * 32, wbase = nb * 32;
    int g = lane >> 2, t4 = lane & 3;
    const char* ysr = ysB + row * 17408;

    float acc[2][4][4];
#pragma unroll
    for (int ms = 0; ms < 2; ms++)
#pragma unroll
        for (int n = 0; n < 4; n++)
#pragma unroll
            for (int j = 0; j < 4; j++) acc[ms][n][j] = 0.f;

#pragma unroll
    for (int k = 0; k < 4; k++) {              // K = 16 per step
        uint32_t a[2][4];
#pragma unroll
        for (int ms = 0; ms < 2; ms++) {
            int r0 = (ob + 16 * ms + g) * 36 + 8 * k + t4;   // u32 units, pitch 36
            a[ms][0] = pw32[r0];
            a[ms][2] = pw32[r0 + 4];
            a[ms][1] = pw32[r0 + 8 * 36];
            a[ms][3] = pw32[r0 + 8 * 36 + 4];
        }
        const char* bR = ysr + (8 * k + t4) * 544;
#pragma unroll
        for (int n = 0; n < 4; n++) {
            int col = (wbase + 8 * n + g) * 4;
            uint32_t b0 = *(const uint32_t*)(bR + col);
            uint32_t b1 = *(const uint32_t*)(bR + 4 * 544 + col);
#pragma unroll
            for (int ms = 0; ms < 2; ms++) {
                asm("mma.sync.aligned.m16n8k16.row.col.f32.f16.f16.f32 "
                    "{%0,%1,%2,%3}, {%4,%5,%6,%7}, {%8,%9}, {%0,%1,%2,%3};"
                    : "+f"(acc[ms][n][0]), "+f"(acc[ms][n][1]),
                      "+f"(acc[ms][n][2]), "+f"(acc[ms][n][3])
                    : "r"(a[ms][0]), "r"(a[ms][1]), "r"(a[ms][2]), "r"(a[ms][3]),
                      "r"(b0), "r"(b1));
            }
        }
    }

    // ---- epilogue: +dbias, store fp16, BN partial stats (fp32) ----
    __half* outb = gOut16 + (size_t)(b * 64) * 16384 + (size_t)(h0 + row) * 128;
    float sAcc[2][2], s2Acc[2][2];
#pragma unroll
    for (int ms = 0; ms < 2; ms++) {
        sAcc[ms][0] = 0.f; sAcc[ms][1] = 0.f;
        s2Acc[ms][0] = 0.f; s2Acc[ms][1] = 0.f;
    }

#pragma unroll
    for (int ms = 0; ms < 2; ms++) {
        int rLo = ob + 16 * ms + g;
        float dbLo = dbs[rLo], dbHi = dbs[rLo + 8];
        size_t oLo = (size_t)rLo * 16384;
        size_t oHi = (size_t)(rLo + 8) * 16384;
#pragma unroll
        for (int n = 0; n < 4; n++) {
            int w = wbase + 8 * n + 2 * t4;
            float v0 = acc[ms][n][0] + dbLo;
            float v1 = acc[ms][n][1] + dbLo;
            float v2 = acc[ms][n][2] + dbHi;
            float v3 = acc[ms][n][3] + dbHi;
            *(__half2*)(outb + oLo + w) = __floats2half2_rn(v0, v1);
            *(__half2*)(outb + oHi + w) = __floats2half2_rn(v2, v3);
            sAcc[ms][0]  += v0 + v1;            s2Acc[ms][0] += v0 * v0 + v1 * v1;
            sAcc[ms][1]  += v2 + v3;            s2Acc[ms][1] += v2 * v2 + v3 * v3;
        }
    }
#pragma unroll
    for (int off = 1; off <= 2; off <<= 1)
#pragma unroll
        for (int ms = 0; ms < 2; ms++)
#pragma unroll
            for (int hl = 0; hl < 2; hl++) {
                sAcc[ms][hl]  += __shfl_xor_sync(0xffffffffu, sAcc[ms][hl],  off);
                s2Acc[ms][hl] += __shfl_xor_sync(0xffffffffu, s2Acc[ms][hl], off);
            }
    if (t4 == 0) {
#pragma unroll
        for (int ms = 0; ms < 2; ms++)
#pragma unroll
            for (int hl = 0; hl < 2; hl++) {
                int o = ob + 16 * ms + 8 * hl + g;
                atomicAdd(&sst[o],      sAcc[ms][hl]);
                atomicAdd(&sst[64 + o], s2Acc[ms][hl]);
            }
    }

    __syncthreads();
    if (tid < 64)       atomicAdd(&gSum[tid],        (double)sst[tid]);
    else if (tid < 128) atomicAdd(&gSumSq[tid - 64], (double)sst[tid]);
}

// =================================================================================
// Kernel 4: BN finalize (per-block, from global stats) + apply   [R12 proven]
//   reads fp16 scratch (uint2 streaming), writes f32 out (one float4/thread); MLP=8
// =================================================================================
__global__ void __launch_bounds__(256) k_bn(float* __restrict__ out,
                                            const float* __restrict__ gamma,
                                            const float* __restrict__ beta)
{
    __shared__ float scS[64], shS[64];
    int t = threadIdx.x;
    if (t < 64) {
        const double n = 524288.0;   // 32 * 128 * 128
        double mean = gSum[t] / n;
        double var  = gSumSq[t] / n - mean * mean;
        double inv  = 1.0 / sqrt(var + 1e-5);
        double gg   = (double)gamma[t];
        scS[t] = (float)(gg * inv);
        shS[t] = (float)((double)beta[t] - mean * gg * inv);
    }
    __syncthreads();

    int base = blockIdx.x * 2048 + threadIdx.x;
    const uint2* src = (const uint2*)gOut16;     // 4 halves per uint2 == 1 float4 slot
    uint2 raw[8];
#pragma unroll
    for (int j = 0; j < 8; j++) raw[j] = __ldcs(src + base + 256 * j);
#pragma unroll
    for (int j = 0; j < 8; j++) {
        int idx = base + 256 * j;
        __half2 hA = *(__half2*)&raw[j].x;
        __half2 hB = *(__half2*)&raw[j].y;
        float2 fA = __half22float2(hA);
        float2 fB = __half22float2(hB);
        int o = (idx >> 12) & 63;                // 4096 float4 per (b,o) plane
        float sc = scS[o], sh = shS[o];
        float4 v;
        v.x = fmaf(fA.x, sc, sh);
        v.y = fmaf(fA.y, sc, sh);
        v.z = fmaf(fB.x, sc, sh);
        v.w = fmaf(fB.y, sc, sh);
        __stcs((float4*)out + idx, v);
    }
}

// =================================================================================
extern "C" void kernel_launch(void* const* d_in, const int* in_sizes, int n_in,
                              void* d_out, int out_size)
{
    const float* x      = (const float*)d_in[0];
    const float* cg_w1  = (const float*)d_in[1];
    const float* cg_b1  = (const float*)d_in[2];
    const float* cg_w2  = (const float*)d_in[3];
    const float* cg_b2  = (const float*)d_in[4];
    const float* wg_w   = (const float*)d_in[5];
    const float* wg_b   = (const float*)d_in[6];
    const float* pg_w   = (const float*)d_in[7];
    const float* pg_b   = (const float*)d_in[8];
    const float* bg_w   = (const float*)d_in[9];
    const float* bg_b   = (const float*)d_in[10];
    const float* bn_g   = (const float*)d_in[11];
    const float* bn_b   = (const float*)d_in[12];
    float* out = (float*)d_out;

    cudaFuncSetAttribute(k_main, cudaFuncAttributeMaxDynamicSharedMemorySize, 47872);

    k_cond_sums<<<2048, 256>>>(x);
    k_gen<<<32, 256>>>(cg_w1, cg_b1, cg_w2, cg_b2, wg_w, wg_b, pg_w, pg_b, bg_w, bg_b);
    dim3 g3(64, 32);
    k_main<<<g3, 512, 47872>>>(x);
    k_bn<<<4096, 256>>>(out, bn_g, bn_b);
}

// round 17
// speedup vs baseline: 1.3428x; 1.0444x over previous
#include <cuda_runtime.h>
#include <cuda_fp16.h>
#include <cstdint>

typedef unsigned long long ull;

// ---------------- device scratch (no runtime allocation allowed) ----------------
__device__ float  gS[32 * 64 * 9];     // strided sums for cond conv
__device__ float  gDw[32 * 576];       // per-sample depthwise weights (fp32)
__device__ __half gPwH[32 * 4096];     // per-sample pointwise weights [b][o][c], fp16
__device__ float  gDb[32 * 64];        // per-sample dynamic bias
__device__ double gSum[64], gSumSq[64];// BN statistics accumulators
__device__ __half gOut16[32 * 64 * 16384];   // pre-BN intermediate (fp16, 67 MB; L2-resident)

// =================================================================================
// Kernel 1: per-(b,c) 9 strided sums, COALESCED; x streamed (evict-first).
// =================================================================================
__global__ void __launch_bounds__(256) k_cond_sums(const float* __restrict__ x) {
    int bc = blockIdx.x;                 // b*64 + c
    int t  = threadIdx.x;
    int lane = t & 31, w = t >> 5;
    const float4* p = (const float4*)(x + (size_t)bc * 16384);

    float bins[9] = {0.f,0.f,0.f,0.f,0.f,0.f,0.f,0.f,0.f};
    float mzw = (lane <= 30) ? 1.f : 0.f;
    float mx2 = (lane >= 1)  ? 1.f : 0.f;

#pragma unroll
    for (int r = 0; r < 16; r++) {
        int i = w * 16 + r;
        float4 v = __ldcs(p + i * 32 + lane);
        float ca0 = v.x + mzw * v.z;
        float ca1 = v.y + mzw * v.w;
        float ca2 = mx2 * v.x + v.z;
        bool ev = ((i & 1) == 0);
        float f0 = (ev  && i <= 124) ? 1.f : 0.f;
        float f1 = (!ev && i <= 125) ? 1.f : 0.f;
        float f2 = (ev  && i >= 2)   ? 1.f : 0.f;
        bins[0] += f0 * ca0;  bins[1] += f0 * ca1;  bins[2] += f0 * ca2;
        bins[3] += f1 * ca0;  bins[4] += f1 * ca1;  bins[5] += f1 * ca2;
        bins[6] += f2 * ca0;  bins[7] += f2 * ca1;  bins[8] += f2 * ca2;
    }

#pragma unroll
    for (int off = 16; off; off >>= 1)
#pragma unroll
        for (int k = 0; k < 9; k++)
            bins[k] += __shfl_down_sync(0xffffffffu, bins[k], off);

    __shared__ float red[8][9];
    if (lane == 0)
#pragma unroll
        for (int k = 0; k < 9; k++) red[w][k] = bins[k];
    __syncthreads();
    if (t < 9) {
        float s = 0.f;
#pragma unroll
        for (int ww = 0; ww < 8; ww++) s += red[ww][t];
        gS[bc * 9 + t] = s;
    }
}

// =================================================================================
// Kernel 2: condition vector + dynamic weights (tiny GEMMs) + stat zeroing
// =================================================================================
__global__ void __launch_bounds__(256) k_gen(
    const float* __restrict__ cg_w1, const float* __restrict__ cg_b1,
    const float* __restrict__ cg_w2, const float* __restrict__ cg_b2,
    const float* __restrict__ wg_w,  const float* __restrict__ wg_b,
    const float* __restrict__ pg_w,  const float* __restrict__ pg_b,
    const float* __restrict__ bg_w,  const float* __restrict__ bg_b)
{
    __shared__ float Ss[576];
    __shared__ float parts[256];
    __shared__ float c0[16];
    __shared__ float cond[16];

    int b = blockIdx.x;
    int t = threadIdx.x;

    // zero BN stat accumulators (runs before k_main in-stream; deterministic)
    if (b == 0 && t < 64) { gSum[t] = 0.0; gSumSq[t] = 0.0; }

    for (int idx = t; idx < 576; idx += 256) Ss[idx] = gS[b * 576 + idx];
    __syncthreads();

    {
        int co = t >> 4, part = t & 15;
        const float* wrow = cg_w1 + co * 576 + part * 36;
        const float* srow = Ss + part * 36;
        float s = 0.f;
#pragma unroll
        for (int k = 0; k < 36; k++) s += wrow[k] * srow[k];
        parts[t] = s;
    }
    __syncthreads();
    if (t < 16) {
        float s = 0.f;
#pragma unroll
        for (int p = 0; p < 16; p++) s += parts[t * 16 + p];
        s = s * (1.0f / 3969.0f) + cg_b1[t];
        c0[t] = fmaxf(s, 0.f);
    }
    __syncthreads();
    if (t < 16) {
        float s = cg_b2[t];
#pragma unroll
        for (int i = 0; i < 16; i++) s += c0[i] * cg_w2[t * 16 + i];
        cond[t] = fmaxf(s, 0.f);
    }
    __syncthreads();

    for (int r = t; r < 576; r += 256) {
        float s = wg_b[r];
        const float* wr = wg_w + r * 16;
#pragma unroll
        for (int q = 0; q < 16; q++) s += cond[q] * wr[q];
        gDw[b * 576 + r] = fmaxf(s, 0.f);
    }
    // pointwise weights [b][o][c], fp16 for the HMMA path
    for (int r = t; r < 4096; r += 256) {
        float s = pg_b[r];
        const float* wr = pg_w + r * 16;
#pragma unroll
        for (int q = 0; q < 16; q++) s += cond[q] * wr[q];
        gPwH[b * 4096 + r] = __float2half(fmaxf(s, 0.f));
    }
    if (t < 64) {
        float s = bg_b[t];
        const float* wr = bg_w + t * 16;
#pragma unroll
        for (int q = 0; q < 16; q++) s += cond[q] * wr[q];
        gDb[b * 64 + t] = s;
    }
}

// =================================================================================
// Kernel 3: fused depthwise3x3 + fp16 MMA (m16n8k16) pointwise, HS=2 rows per CTA.
//   512 threads; 2 CTAs/SM; grid (64, 32). x streamed; writes fp16 pre-BN tensor.
// smem (floats):
//   ysH [2 row][32 c2][136 half2]  offset 0     (8704 fl)
//   pwH [64 o][72 half]            offset 8704  (2304 fl)
//   dws [64 c][12]                 offset 11008 (768 fl)
//   dbs [64]                       offset 11776
//   sst [128]                      offset 11840  -> 11968 fl = 47872 B
// =================================================================================
__global__ void __launch_bounds__(512, 2) k_main(const float* __restrict__ x)
{
    extern __shared__ float sm[];
    char*  ysB = (char*)sm;                       // byte base of ysH
    const uint32_t* pw32 = (const uint32_t*)(sm + 8704);  // pwH as u32 (2 halves)
    float* dws = sm + 11008;
    float* dbs = sm + 11776;
    float* sst = sm + 11840;

    int tid  = threadIdx.x;
    int lane = tid & 31, wid = tid >> 5;
    int h0 = blockIdx.x * 2, b = blockIdx.y;

    // ---- stage per-sample dynamic weights into smem ----
    {
        // pw fp16: 4096 halves = 512 uint4; pad rows to 72 halves (144 B)
        const uint4* src = (const uint4*)(gPwH + b * 4096);
        uint4 v = src[tid];
        int o = tid >> 3, j = tid & 7;
        *(uint4*)((char*)(sm + 8704) + o * 144 + j * 16) = v;

        for (int idx = tid; idx < 576; idx += 512) {
            int c = idx / 9, jj = idx - 9 * c;
            dws[c * 12 + jj] = gDw[b * 576 + idx];
        }
        if (tid < 64) dbs[tid] = gDb[b * 64 + tid];
        else if (tid >= 64 && tid < 192) sst[tid - 64] = 0.f;
    }
    __syncthreads();

    // ---- depthwise 3x3 (pad=1); warp w: channels [4w,4w+4) = 2 pairs; 2 rows ----
    const float4* xb = (const float4*)(x + (size_t)b * 64 * 16384);
    const float4 z4 = make_float4(0.f, 0.f, 0.f, 0.f);
    bool hasT = (h0 >= 1), hasB = (h0 <= 125);

#pragma unroll
    for (int pr = 0; pr < 2; pr++) {
        float rE[2][4], rO[2][4];
#pragma unroll
        for (int half = 0; half < 2; half++) {
            int c = wid * 4 + pr * 2 + half;
            const float4* plane = xb + (size_t)c * 4096;
            float4 m[4];
            m[0] = hasT ? __ldcs(plane + (h0 - 1) * 32 + lane) : z4;
            m[1] =        __ldcs(plane + h0       * 32 + lane);
            m[2] =        __ldcs(plane + (h0 + 1) * 32 + lane);
            m[3] = hasB ? __ldcs(plane + (h0 + 2) * 32 + lane) : z4;

            float lf[4], rg[4];
#pragma unroll
            for (int i = 0; i < 4; i++) {
                lf[i] = __shfl_up_sync(0xffffffffu, m[i].w, 1);
                rg[i] = __shfl_down_sync(0xffffffffu, m[i].x, 1);
                if (lane == 0)  lf[i] = 0.f;
                if (lane == 31) rg[i] = 0.f;
            }

            const float* wp = dws + c * 12;
            float4 wA = *(const float4*)(wp);       // w00 w01 w02 w10
            float4 wB = *(const float4*)(wp + 4);   // w11 w12 w20 w21
            float  w8 = wp[8];                      // w22

#pragma unroll
            for (int row = 0; row < 2; row++) {
                float a0 = 0.f, a1 = 0.f, a2 = 0.f, a3 = 0.f;
#pragma unroll
                for (int r = 0; r < 3; r++) {
                    int i = row + r;
                    float w0 = (r == 0) ? wA.x : (r == 1) ? wA.w : wB.z;
                    float w1 = (r == 0) ? wA.y : (r == 1) ? wB.x : wB.w;
                    float w2 = (r == 0) ? wA.z : (r == 1) ? wB.y : w8;
                    a0 += w0 * lf[i]  + w1 * m[i].x + w2 * m[i].y;
                    a1 += w0 * m[i].x + w1 * m[i].y + w2 * m[i].z;
                    a2 += w0 * m[i].y + w1 * m[i].z + w2 * m[i].w;
                    a3 += w0 * m[i].z + w1 * m[i].w + w2 * rg[i];
                }
                float* dst = half ? rO[row] : rE[row];
                dst[0] = a0; dst[1] = a1; dst[2] = a2; dst[3] = a3;
            }
        }
        // pack channel pair -> half2 (low = even channel = lower k) and store
        int c2 = wid * 2 + pr;
#pragma unroll
        for (int row = 0; row < 2; row++) {
            __half2 h0p = __floats2half2_rn(rE[row][0], rO[row][0]);
            __half2 h1p = __floats2half2_rn(rE[row][1], rO[row][1]);
            __half2 h2p = __floats2half2_rn(rE[row][2], rO[row][2]);
            __half2 h3p = __floats2half2_rn(rE[row][3], rO[row][3]);
            uint4 v;
            v.x = *(uint32_t*)&h0p; v.y = *(uint32_t*)&h1p;
            v.z = *(uint32_t*)&h2p; v.w = *(uint32_t*)&h3p;
            *(uint4*)(ysB + row * 17408 + c2 * 544 + lane * 16) = v;
        }
    }
    __syncthreads();

    // ---- fp16 MMA pointwise: warp -> (row, mt, nb); M32 x N32 tile ----
    int row = wid >> 3, mt = (wid >> 2) & 1, nb = wid & 3;
    int ob = mt * 32, wbase = nb * 32;
    int g = lane >> 2, t4 = lane & 3;
    const char* ysr = ysB + row * 17408;

    float acc[2][4][4];
#pragma unroll
    for (int ms = 0; ms < 2; ms++)
#pragma unroll
        for (int n = 0; n < 4; n++)
#pragma unroll
            for (int j = 0; j < 4; j++) acc[ms][n][j] = 0.f;

#pragma unroll
    for (int k = 0; k < 4; k++) {              // K = 16 per step
        uint32_t a[2][4];
#pragma unroll
        for (int ms = 0; ms < 2; ms++) {
            int r0 = (ob + 16 * ms + g) * 36 + 8 * k + t4;   // u32 units, pitch 36
            a[ms][0] = pw32[r0];
            a[ms][2] = pw32[r0 + 4];
            a[ms][1] = pw32[r0 + 8 * 36];
            a[ms][3] = pw32[r0 + 8 * 36 + 4];
        }
        const char* bR = ysr + (8 * k + t4) * 544;
#pragma unroll
        for (int n = 0; n < 4; n++) {
            int col = (wbase + 8 * n + g) * 4;
            uint32_t b0 = *(const uint32_t*)(bR + col);
            uint32_t b1 = *(const uint32_t*)(bR + 4 * 544 + col);
#pragma unroll
            for (int ms = 0; ms < 2; ms++) {
                asm("mma.sync.aligned.m16n8k16.row.col.f32.f16.f16.f32 "
                    "{%0,%1,%2,%3}, {%4,%5,%6,%7}, {%8,%9}, {%0,%1,%2,%3};"
                    : "+f"(acc[ms][n][0]), "+f"(acc[ms][n][1]),
                      "+f"(acc[ms][n][2]), "+f"(acc[ms][n][3])
                    : "r"(a[ms][0]), "r"(a[ms][1]), "r"(a[ms][2]), "r"(a[ms][3]),
                      "r"(b0), "r"(b1));
            }
        }
    }

    // ---- epilogue: +dbias, store fp16 (L2-resident), BN partial stats (fp32) ----
    __half* outb = gOut16 + (size_t)(b * 64) * 16384 + (size_t)(h0 + row) * 128;
    float sAcc[2][2], s2Acc[2][2];
#pragma unroll
    for (int ms = 0; ms < 2; ms++) {
        sAcc[ms][0] = 0.f; sAcc[ms][1] = 0.f;
        s2Acc[ms][0] = 0.f; s2Acc[ms][1] = 0.f;
    }

#pragma unroll
    for (int ms = 0; ms < 2; ms++) {
        int rLo = ob + 16 * ms + g;
        float dbLo = dbs[rLo], dbHi = dbs[rLo + 8];
        size_t oLo = (size_t)rLo * 16384;
        size_t oHi = (size_t)(rLo + 8) * 16384;
#pragma unroll
        for (int n = 0; n < 4; n++) {
            int w = wbase + 8 * n + 2 * t4;
            float v0 = acc[ms][n][0] + dbLo;
            float v1 = acc[ms][n][1] + dbLo;
            float v2 = acc[ms][n][2] + dbHi;
            float v3 = acc[ms][n][3] + dbHi;
            *(__half2*)(outb + oLo + w) = __floats2half2_rn(v0, v1);
            *(__half2*)(outb + oHi + w) = __floats2half2_rn(v2, v3);
            sAcc[ms][0]  += v0 + v1;            s2Acc[ms][0] += v0 * v0 + v1 * v1;
            sAcc[ms][1]  += v2 + v3;            s2Acc[ms][1] += v2 * v2 + v3 * v3;
        }
    }
#pragma unroll
    for (int off = 1; off <= 2; off <<= 1)
#pragma unroll
        for (int ms = 0; ms < 2; ms++)
#pragma unroll
            for (int hl = 0; hl < 2; hl++) {
                sAcc[ms][hl]  += __shfl_xor_sync(0xffffffffu, sAcc[ms][hl],  off);
                s2Acc[ms][hl] += __shfl_xor_sync(0xffffffffu, s2Acc[ms][hl], off);
            }
    if (t4 == 0) {
#pragma unroll
        for (int ms = 0; ms < 2; ms++)
#pragma unroll
            for (int hl = 0; hl < 2; hl++) {
                int o = ob + 16 * ms + 8 * hl + g;
                atomicAdd(&sst[o],      sAcc[ms][hl]);
                atomicAdd(&sst[64 + o], s2Acc[ms][hl]);
            }
    }

    __syncthreads();
    if (tid < 64)       atomicAdd(&gSum[tid],        (double)sst[tid]);
    else if (tid < 128) atomicAdd(&gSumSq[tid - 64], (double)sst[tid]);
}

// =================================================================================
// Kernel 4: BN finalize (per-block, from global stats) + apply
//   reads fp16 scratch (L2-resident, evict-after-read), streams f32 out; MLP=8
// =================================================================================
__global__ void __launch_bounds__(256) k_bn(float* __restrict__ out,
                                            const float* __restrict__ gamma,
                                            const float* __restrict__ beta)
{
    __shared__ float scS[64], shS[64];
    int t = threadIdx.x;
    if (t < 64) {
        const double n = 524288.0;   // 32 * 128 * 128
        double mean = gSum[t] / n;
        double var  = gSumSq[t] / n - mean * mean;
        double inv  = 1.0 / sqrt(var + 1e-5);
        double gg   = (double)gamma[t];
        scS[t] = (float)(gg * inv);
        shS[t] = (float)((double)beta[t] - mean * gg * inv);
    }
    __syncthreads();

    int base = blockIdx.x * 2048 + threadIdx.x;
    const uint2* src = (const uint2*)gOut16;     // 4 halves per uint2 == 1 float4 slot
    uint2 raw[8];
#pragma unroll
    for (int j = 0; j < 8; j++) raw[j] = __ldcs(src + base + 256 * j);
#pragma unroll
    for (int j = 0; j < 8; j++) {
        int idx = base + 256 * j;
        __half2 hA = *(__half2*)&raw[j].x;
        __half2 hB = *(__half2*)&raw[j].y;
        float2 fA = __half22float2(hA);
        float2 fB = __half22float2(hB);
        int o = (idx >> 12) & 63;                // 4096 float4 per (b,o) plane
        float sc = scS[o], sh = shS[o];
        float4 v;
        v.x = fmaf(fA.x, sc, sh);
        v.y = fmaf(fA.y, sc, sh);
        v.z = fmaf(fB.x, sc, sh);
        v.w = fmaf(fB.y, sc, sh);
        __stcs((float4*)out + idx, v);
    }
}

// =================================================================================
extern "C" void kernel_launch(void* const* d_in, const int* in_sizes, int n_in,
                              void* d_out, int out_size)
{
    const float* x      = (const float*)d_in[0];
    const float* cg_w1  = (const float*)d_in[1];
    const float* cg_b1  = (const float*)d_in[2];
    const float* cg_w2  = (const float*)d_in[3];
    const float* cg_b2  = (const float*)d_in[4];
    const float* wg_w   = (const float*)d_in[5];
    const float* wg_b   = (const float*)d_in[6];
    const float* pg_w   = (const float*)d_in[7];
    const float* pg_b   = (const float*)d_in[8];
    const float* bg_w   = (const float*)d_in[9];
    const float* bg_b   = (const float*)d_in[10];
    const float* bn_g   = (const float*)d_in[11];
    const float* bn_b   = (const float*)d_in[12];
    float* out = (float*)d_out;

    cudaFuncSetAttribute(k_main, cudaFuncAttributeMaxDynamicSharedMemorySize, 47872);

    k_cond_sums<<<2048, 256>>>(x);
    k_gen<<<32, 256>>>(cg_w1, cg_b1, cg_w2, cg_b2, wg_w, wg_b, pg_w, pg_b, bg_w, bg_b);
    dim3 g3(64, 32);
    k_main<<<g3, 512, 47872>>>(x);
    k_bn<<<4096, 256>>>(out, bn_g, bn_b);
}